// round 10
// baseline (speedup 1.0000x reference)
#include <cuda_runtime.h>

// Problem constants (fixed by the dataset)
#define NB    128          // graphs (B)
#define NN    256          // nodes per graph
#define DPE   16           // D_pe / eigen dim
#define MM    4            // M psi copies
#define HPSI  32
#define HP    16
#define HG    64
#define NSUM  (NB*NN)      // 32768
#define EDGES (NSUM*16)    // 524288
#define EPG   (EDGES/NB)   // 4096 edges per graph (graph-contiguous)
#define PSTR  257          // u64 plane stride (odd -> staggered banks)

typedef unsigned long long u64;

// Scratch (device globals: no allocation allowed)
__device__ float g_x[NSUM*HP];           // pooled features
__device__ int   g_srt[EDGES];           // CSR: src sorted by dst (per graph)
__device__ int   g_start[NB*(NN+1)];     // CSR row starts (stride 257)

// ---------------- packed f32x2 helpers ----------------
__device__ __forceinline__ u64 pk2(float lo, float hi) {
    u64 r; asm("mov.b64 %0,{%1,%2};" : "=l"(r) : "f"(lo), "f"(hi)); return r;
}
__device__ __forceinline__ void upk2(u64 v, float& lo, float& hi) {
    asm("mov.b64 {%0,%1},%2;" : "=f"(lo), "=f"(hi) : "l"(v));
}
__device__ __forceinline__ u64 fma2(u64 a, u64 b, u64 c) {
    u64 d; asm("fma.rn.f32x2 %0,%1,%2,%3;" : "=l"(d) : "l"(a), "l"(b), "l"(c)); return d;
}
__device__ __forceinline__ u64 mul2(u64 a, u64 b) {
    u64 d; asm("mul.rn.f32x2 %0,%1,%2;" : "=l"(d) : "l"(a), "l"(b)); return d;
}
__device__ __forceinline__ u64 add2(u64 a, u64 b) {
    u64 d; asm("add.rn.f32x2 %0,%1,%2;" : "=l"(d) : "l"(a), "l"(b)); return d;
}

// ---------------------------------------------------------------------------
// Fused kernel B: blocks [0,NB) = pairwise phase; blocks [NB,2NB) = CSR build.
// V tile and exchange buffers stored as 8 u64 channel-planes (stride PSTR):
// gather/exchange accesses are bank-conflict-free (consecutive lanes ->
// consecutive u64 within a plane).
// ---------------------------------------------------------------------------
#define COMPUTE_R2(kk) do {                                                     \
    u64 vk_[8];                                                                 \
    _Pragma("unroll")                                                           \
    for (int j_ = 0; j_ < 8; j_++) vk_[j_] = VsP[j_*PSTR + (kk)];               \
    u64 wm_[4];                                                                 \
    _Pragma("unroll")                                                           \
    for (int m_ = 0; m_ < 4; m_++) {                                            \
        u64 s_ = mul2(An2[m_][0], vk_[0]);                                      \
        _Pragma("unroll")                                                       \
        for (int j_ = 1; j_ < 8; j_++) s_ = fma2(An2[m_][j_], vk_[j_], s_);     \
        float lo_, hi_; upk2(s_, lo_, hi_);                                     \
        float w_ = lo_ + hi_;                                                   \
        wm_[m_] = pk2(w_, w_);                                                  \
    }                                                                           \
    _Pragma("unroll")                                                           \
    for (int hp_ = 0; hp_ < 8; hp_++) {                                         \
        u64 p_ = fma2(wm_[0], wp2[0][hp_], bps2[hp_]);                          \
        p_ = fma2(wm_[1], wp2[1][hp_], p_);                                     \
        p_ = fma2(wm_[2], wp2[2][hp_], p_);                                     \
        p_ = fma2(wm_[3], wp2[3][hp_], p_);                                     \
        float lo_, hi_; upk2(p_, lo_, hi_);                                     \
        lo_ = fmaxf(lo_, 0.f); hi_ = fmaxf(hi_, 0.f);                           \
        rp[hp_] = pk2(lo_, hi_);                                                \
    }                                                                           \
} while (0)

__global__ void __launch_bounds__(256) kernelB(
        const float* __restrict__ V,
        const float* __restrict__ Lambda,
        const float* __restrict__ pW1, const float* __restrict__ pb1,
        const float* __restrict__ pW2, const float* __restrict__ pb2,
        const float* __restrict__ Wp1, const float* __restrict__ bp1,
        const int*   __restrict__ batch,
        const int*   __restrict__ edge_index)
{
    extern __shared__ __align__(16) u64 smu[];
    int n = threadIdx.x;

    // ======================= CSR blocks =======================
    if (blockIdx.x >= NB) {
        int b = blockIdx.x - NB;
        int t = n;
        int* ism  = (int*)smu;
        int* cnt  = ism;             // 256
        int* cur  = ism + NN;        // 256
        int* wsum = ism + 2*NN;      // 8
        int* dstc = ism + 2*NN + 8;  // 4096

        int base = b*NN;
        cnt[t] = 0;
        __syncthreads();

        const int* srcp = edge_index + (size_t)b*EPG;
        const int* dstp = edge_index + (size_t)EDGES + (size_t)b*EPG;

        #pragma unroll
        for (int e = t; e < EPG; e += 256) {
            int d = dstp[e] - base;
            dstc[e] = d;
            atomicAdd(&cnt[d], 1);
        }
        __syncthreads();

        int v = cnt[t];
        int incl = v;
        #pragma unroll
        for (int off = 1; off < 32; off <<= 1) {
            int x = __shfl_up_sync(0xffffffffu, incl, off);
            if ((t & 31) >= off) incl += x;
        }
        if ((t & 31) == 31) wsum[t >> 5] = incl;
        __syncthreads();
        if (t == 0) {
            int s = 0;
            #pragma unroll
            for (int i = 0; i < 8; i++) { int x = wsum[i]; wsum[i] = s; s += x; }
        }
        __syncthreads();
        int excl = incl - v + wsum[t >> 5];
        g_start[b*(NN+1) + t] = excl;
        if (t == 0) g_start[b*(NN+1) + NN] = EPG;
        cur[t] = excl;
        __syncthreads();

        #pragma unroll
        for (int e = t; e < EPG; e += 256) {
            int pos = atomicAdd(&cur[dstc[e]], 1);
            g_srt[(size_t)b*EPG + pos] = srcp[e] - base;
        }
        return;
    }

    // ======================= pairwise blocks =======================
    u64*   VsP  = smu;               // 8 planes x PSTR u64
    u64*   xchA = smu + 8*PSTR;      // exchange buffer A (planes)
    u64*   xchB = smu + 16*PSTR;     // exchange buffer B (planes)
    float* zs   = (float*)(smu + 24*PSTR);   // 64 floats
    __shared__ int bnds[2];

    int b = blockIdx.x;

    // Stage V row n into the 8 channel planes (conflict-free STS.64)
    {
        const float4* vg = (const float4*)(V + (size_t)b*NN*DPE);
        float4 q0 = vg[n*4 + 0], q1 = vg[n*4 + 1], q2 = vg[n*4 + 2], q3 = vg[n*4 + 3];
        VsP[0*PSTR + n] = pk2(q0.x, q0.y);
        VsP[1*PSTR + n] = pk2(q0.z, q0.w);
        VsP[2*PSTR + n] = pk2(q1.x, q1.y);
        VsP[3*PSTR + n] = pk2(q1.z, q1.w);
        VsP[4*PSTR + n] = pk2(q2.x, q2.y);
        VsP[5*PSTR + n] = pk2(q2.z, q2.w);
        VsP[6*PSTR + n] = pk2(q3.x, q3.y);
        VsP[7*PSTR + n] = pk2(q3.z, q3.w);
    }

    // psi MLP (threads 0..63), eigen-count via binary search (threads 0,1)
    float pacc = 0.f;
    if (n < DPE*MM) {
        int d = n >> 2, m = n & 3;
        float lam = Lambda[b*DPE + d];
        pacc = pb2[m];
        #pragma unroll
        for (int h = 0; h < HPSI; h++) {
            float v = fmaf(lam, pW1[m*HPSI + h], pb1[m*HPSI + h]);
            pacc = fmaf(fmaxf(v, 0.f), pW2[m*HPSI + h], pacc);
        }
    }
    if (n < 2) {
        int key = b + n;            // first index with batch[i] >= key
        int lo = 0, hi = NSUM;
        while (lo < hi) {
            int mid = (lo + hi) >> 1;
            if (batch[mid] < key) lo = mid + 1; else hi = mid;
        }
        bnds[n] = lo;
    }

    // Projection weights, packed, in registers
    u64 wp2[MM][HP/2];
    u64 bps2[HP/2];
    #pragma unroll
    for (int m = 0; m < MM; m++)
        #pragma unroll
        for (int hp = 0; hp < HP/2; hp++)
            wp2[m][hp] = pk2(Wp1[m*HP + 2*hp], Wp1[m*HP + 2*hp + 1]);
    #pragma unroll
    for (int hp = 0; hp < HP/2; hp++) bps2[hp] = pk2(bp1[2*hp], bp1[2*hp+1]);

    __syncthreads();
    if (n < DPE*MM) {
        int cnt = bnds[1] - bnds[0];
        zs[n] = ((n >> 2) < cnt) ? pacc : 0.f;
    }
    __syncthreads();

    // Per-thread packed scaled row: An2[m][j] = (V[n,2j]Z[2j,m], V[n,2j+1]Z[2j+1,m])
    u64 An2[MM][DPE/2];
    {
        float vn[DPE];
        #pragma unroll
        for (int j = 0; j < 8; j++) {
            u64 v2 = VsP[j*PSTR + n];
            upk2(v2, vn[2*j], vn[2*j+1]);
        }
        #pragma unroll
        for (int j = 0; j < 8; j++) {
            #pragma unroll
            for (int m = 0; m < MM; m++)
                An2[m][j] = pk2(vn[2*j] * zs[(2*j)*MM + m],
                                vn[2*j+1] * zs[(2*j+1)*MM + m]);
        }
    }

    u64 acc2[HP/2];
    #pragma unroll
    for (int h = 0; h < HP/2; h++) acc2[h] = 0ull;

    u64 rp[8];

    // o = 0: diagonal pair (n,n) counted once
    {
        COMPUTE_R2(n);
        #pragma unroll
        for (int h = 0; h < 8; h++) acc2[h] = add2(acc2[h], rp[h]);
    }

    // o = 1..128: each unordered pair computed exactly once
    for (int o = 1; o <= 128; o++) {
        int  k   = (n + o) & 255;
        bool act = (o < 128) || (n < 128);   // o=128: only lower half computes
        u64* xch = (o & 1) ? xchB : xchA;
        if (act) {
            COMPUTE_R2(k);
            #pragma unroll
            for (int h = 0; h < 8; h++) {
                acc2[h] = add2(acc2[h], rp[h]);
                xch[h*PSTR + n] = rp[h];          // conflict-free STS.64
            }
        }
        __syncthreads();
        if (o < 128 || n >= 128) {
            int j = (n - o) & 255;
            #pragma unroll
            for (int h = 0; h < 8; h++)
                acc2[h] = add2(acc2[h], xch[h*PSTR + j]);   // conflict-free LDS.64
        }
    }

    ulonglong2* xo = (ulonglong2*)(g_x + (size_t)(b*NN + n)*HP);
    xo[0] = make_ulonglong2(acc2[0], acc2[1]);
    xo[1] = make_ulonglong2(acc2[2], acc2[3]);
    xo[2] = make_ulonglong2(acc2[4], acc2[5]);
    xo[3] = make_ulonglong2(acc2[6], acc2[7]);
}

// ---------------------------------------------------------------------------
// Kernel D: gather + GIN MLP. 1 CTA/graph, 512 threads = 2 threads per node
// (channel split). Gather from transposed u64 planes. (Unchanged from R9.)
// ---------------------------------------------------------------------------
__global__ void __launch_bounds__(512) kernelD(
        const float* __restrict__ Wg1, const float* __restrict__ bg1,
        const float* __restrict__ Wg2, const float* __restrict__ bg2,
        const float* __restrict__ eps, float* __restrict__ out)
{
    __shared__ __align__(16) u64   xsT[8*PSTR];     // 16456 B transposed planes
    __shared__ __align__(16) int   srts[EPG];       // 16384 B
    __shared__ __align__(16) float Wg1s[HP*HG];     //  4096 B
    __shared__ __align__(16) float Wg2s[HG*DPE];    //  4096 B
    __shared__ __align__(16) float bg1s[HG];
    __shared__ __align__(16) float bg2s[DPE];

    int b = blockIdx.x;
    int t = threadIdx.x;         // 0..511
    int node = t >> 1;
    int half = t & 1;

    // Stage srt (int4 bulk)
    {
        const int4* sg = (const int4*)(g_srt + (size_t)b*EPG);
        int4* ss = (int4*)srts;
        #pragma unroll
        for (int i = t; i < EPG/4; i += 512) ss[i] = sg[i];
    }
    // Stage x TRANSPOSED: plane j holds channels (2j, 2j+1) as one u64 per node
    {
        const float4* xg = (const float4*)(g_x + (size_t)b*NN*HP);
        for (int i = t; i < NN*4; i += 512) {
            int nd = i >> 2, qd = i & 3;
            float4 a = xg[i];
            xsT[(2*qd)*PSTR + nd]     = pk2(a.x, a.y);
            xsT[(2*qd + 1)*PSTR + nd] = pk2(a.z, a.w);
        }
    }
    for (int i = t; i < HP*HG;  i += 512) Wg1s[i] = Wg1[i];
    for (int i = t; i < HG*DPE; i += 512) Wg2s[i] = Wg2[i];
    if (t < HG)  bg1s[t] = bg1[t];
    if (t >= 512 - DPE) bg2s[t - (512 - DPE)] = bg2[t - (512 - DPE)];
    __syncthreads();

    int s0 = g_start[b*(NN+1) + node];
    int s1 = g_start[b*(NN+1) + node + 1];

    const u64* p0 = &xsT[(4*half + 0)*PSTR];
    const u64* p1 = &xsT[(4*half + 1)*PSTR];
    const u64* p2 = &xsT[(4*half + 2)*PSTR];
    const u64* p3 = &xsT[(4*half + 3)*PSTR];

    u64 agg[4];
    agg[0] = agg[1] = agg[2] = agg[3] = 0ull;
    int idx = s0;
    for (; idx + 2 <= s1; idx += 2) {
        int ea = srts[idx], eb = srts[idx + 1];
        u64 a0 = p0[ea], a1 = p1[ea], a2 = p2[ea], a3 = p3[ea];
        u64 b0 = p0[eb], b1 = p1[eb], b2 = p2[eb], b3 = p3[eb];
        agg[0] = add2(agg[0], a0); agg[1] = add2(agg[1], a1);
        agg[2] = add2(agg[2], a2); agg[3] = add2(agg[3], a3);
        agg[0] = add2(agg[0], b0); agg[1] = add2(agg[1], b1);
        agg[2] = add2(agg[2], b2); agg[3] = add2(agg[3], b3);
    }
    if (idx < s1) {
        int e = srts[idx];
        agg[0] = add2(agg[0], p0[e]); agg[1] = add2(agg[1], p1[e]);
        agg[2] = add2(agg[2], p2[e]); agg[3] = add2(agg[3], p3[e]);
    }

    float ge = 1.f + eps[0];
    u64 ge2 = pk2(ge, ge);
    u64 ymine[4];
    ymine[0] = fma2(ge2, p0[node], agg[0]);
    ymine[1] = fma2(ge2, p1[node], agg[1]);
    ymine[2] = fma2(ge2, p2[node], agg[2]);
    ymine[3] = fma2(ge2, p3[node], agg[3]);

    u64 yfull[8];
    #pragma unroll
    for (int j = 0; j < 4; j++) {
        u64 yo = __shfl_xor_sync(0xffffffffu, ymine[j], 1);
        yfull[4*half + j] = ymine[j];
        yfull[4*(1-half) + j] = yo;
    }

    u64 tg[16];
    {
        const u64* bu = (const u64*)bg1s;
        #pragma unroll
        for (int j = 0; j < 16; j++) tg[j] = bu[16*half + j];
    }
    #pragma unroll
    for (int hq = 0; hq < 8; hq++) {
        float ylo, yhi; upk2(yfull[hq], ylo, yhi);
        u64 ya = pk2(ylo, ylo), yb = pk2(yhi, yhi);
        const ulonglong2* wa = (const ulonglong2*)&Wg1s[(2*hq)*HG   + 32*half];
        const ulonglong2* wb = (const ulonglong2*)&Wg1s[(2*hq+1)*HG + 32*half];
        #pragma unroll
        for (int jj = 0; jj < 8; jj++) {
            ulonglong2 A = wa[jj];
            tg[2*jj]   = fma2(ya, A.x, tg[2*jj]);
            tg[2*jj+1] = fma2(ya, A.y, tg[2*jj+1]);
        }
        #pragma unroll
        for (int jj = 0; jj < 8; jj++) {
            ulonglong2 Bv = wb[jj];
            tg[2*jj]   = fma2(yb, Bv.x, tg[2*jj]);
            tg[2*jj+1] = fma2(yb, Bv.y, tg[2*jj+1]);
        }
    }

    u64 o2[8];
    {
        const u64* bu = (const u64*)bg2s;
        #pragma unroll
        for (int d = 0; d < 8; d++) o2[d] = half ? 0ull : bu[d];
    }
    #pragma unroll
    for (int j = 0; j < 16; j++) {
        float t0, t1; upk2(tg[j], t0, t1);
        t0 = fmaxf(t0, 0.f); t1 = fmaxf(t1, 0.f);
        u64 ta = pk2(t0, t0), tb = pk2(t1, t1);
        int r0 = 32*half + 2*j;
        const ulonglong2* wa = (const ulonglong2*)&Wg2s[r0*DPE];
        const ulonglong2* wb = (const ulonglong2*)&Wg2s[(r0+1)*DPE];
        #pragma unroll
        for (int d = 0; d < 4; d++) {
            ulonglong2 A = wa[d], Bv = wb[d];
            o2[2*d]   = fma2(ta, A.x,  o2[2*d]);
            o2[2*d+1] = fma2(ta, A.y,  o2[2*d+1]);
            o2[2*d]   = fma2(tb, Bv.x, o2[2*d]);
            o2[2*d+1] = fma2(tb, Bv.y, o2[2*d+1]);
        }
    }
    #pragma unroll
    for (int d = 0; d < 8; d++) {
        u64 oo = __shfl_xor_sync(0xffffffffu, o2[d], 1);
        o2[d] = add2(o2[d], oo);
    }

    if (half == 0) {
        ulonglong2* op = (ulonglong2*)(out + (size_t)(b*NN + node)*DPE);
        op[0] = make_ulonglong2(o2[0], o2[1]);
        op[1] = make_ulonglong2(o2[2], o2[3]);
        op[2] = make_ulonglong2(o2[4], o2[5]);
        op[3] = make_ulonglong2(o2[6], o2[7]);
    }
}

// ---------------------------------------------------------------------------
extern "C" void kernel_launch(void* const* d_in, const int* in_sizes, int n_in,
                              void* d_out, int out_size)
{
    const float* Lambda = (const float*)d_in[0];
    const float* V      = (const float*)d_in[1];
    const float* pW1    = (const float*)d_in[2];
    const float* pb1    = (const float*)d_in[3];
    const float* pW2    = (const float*)d_in[4];
    const float* pb2    = (const float*)d_in[5];
    const float* Wp1    = (const float*)d_in[6];
    const float* bp1    = (const float*)d_in[7];
    const float* Wg1    = (const float*)d_in[8];
    const float* bg1    = (const float*)d_in[9];
    const float* Wg2    = (const float*)d_in[10];
    const float* bg2    = (const float*)d_in[11];
    const float* eps    = (const float*)d_in[12];
    const int*   edge_index = (const int*)d_in[13];
    const int*   batch  = (const int*)d_in[14];
    float* out = (float*)d_out;

    // 24 planes of PSTR u64 + 64 floats = 24*257*8 + 256 = 49600 bytes
    const int smemB = 24*PSTR*8 + 256;
    cudaFuncSetAttribute(kernelB, cudaFuncAttributeMaxDynamicSharedMemorySize, smemB);

    kernelB<<<NB*2, 256, smemB>>>(V, Lambda, pW1, pb1, pW2, pb2, Wp1, bp1,
                                  batch, edge_index);
    kernelD<<<NB, 512>>>(Wg1, bg1, Wg2, bg2, eps, out);
}

// round 11
// speedup vs baseline: 1.2131x; 1.2131x over previous
#include <cuda_runtime.h>

// Problem constants (fixed by the dataset)
#define NB    128          // graphs (B)
#define NN    256          // nodes per graph
#define DPE   16           // D_pe / eigen dim
#define MM    4            // M psi copies
#define HPSI  32
#define HP    16
#define HG    64
#define NSUM  (NB*NN)      // 32768
#define EDGES (NSUM*16)    // 524288
#define EPG   (EDGES/NB)   // 4096 edges per graph (graph-contiguous)
#define VPAD  20           // padded row stride (floats)

typedef unsigned long long u64;

// Scratch (device globals: no allocation allowed)
__device__ float g_x[NSUM*HP];           // pooled features
__device__ int   g_srt[EDGES];           // CSR: src sorted by dst (per graph)
__device__ int   g_start[NB*(NN+1)];     // CSR row starts (stride 257)

// ---------------- packed f32x2 helpers ----------------
__device__ __forceinline__ u64 pk2(float lo, float hi) {
    u64 r; asm("mov.b64 %0,{%1,%2};" : "=l"(r) : "f"(lo), "f"(hi)); return r;
}
__device__ __forceinline__ void upk2(u64 v, float& lo, float& hi) {
    asm("mov.b64 {%0,%1},%2;" : "=f"(lo), "=f"(hi) : "l"(v));
}
__device__ __forceinline__ u64 fma2(u64 a, u64 b, u64 c) {
    u64 d; asm("fma.rn.f32x2 %0,%1,%2,%3;" : "=l"(d) : "l"(a), "l"(b), "l"(c)); return d;
}
__device__ __forceinline__ u64 mul2(u64 a, u64 b) {
    u64 d; asm("mul.rn.f32x2 %0,%1,%2;" : "=l"(d) : "l"(a), "l"(b)); return d;
}
__device__ __forceinline__ u64 add2(u64 a, u64 b) {
    u64 d; asm("add.rn.f32x2 %0,%1,%2;" : "=l"(d) : "l"(a), "l"(b)); return d;
}

// ---------------------------------------------------------------------------
// Fused kernel B: blocks [0,NB) = pairwise phase; blocks [NB,2NB) = CSR build.
// Pairwise: offsets processed 4 per barrier (double-buffered 2x4 exchange
// buffers) -> 32 barriers instead of 128, 4x ILP between barriers.
// ---------------------------------------------------------------------------
#define COMPUTE_R2(kk) do {                                                     \
    const ulonglong2* vr_ = (const ulonglong2*)&Vs[(kk)*VPAD];                  \
    ulonglong2 a_ = vr_[0], b_ = vr_[1], c_ = vr_[2], d_ = vr_[3];              \
    u64 vk_[8] = {a_.x, a_.y, b_.x, b_.y, c_.x, c_.y, d_.x, d_.y};              \
    u64 wm_[4];                                                                 \
    _Pragma("unroll")                                                           \
    for (int m_ = 0; m_ < 4; m_++) {                                            \
        u64 s_ = mul2(An2[m_][0], vk_[0]);                                      \
        _Pragma("unroll")                                                       \
        for (int j_ = 1; j_ < 8; j_++) s_ = fma2(An2[m_][j_], vk_[j_], s_);     \
        float lo_, hi_; upk2(s_, lo_, hi_);                                     \
        float w_ = lo_ + hi_;                                                   \
        wm_[m_] = pk2(w_, w_);                                                  \
    }                                                                           \
    _Pragma("unroll")                                                           \
    for (int hp_ = 0; hp_ < 8; hp_++) {                                         \
        u64 p_ = fma2(wm_[0], wp2[0][hp_], bps2[hp_]);                          \
        p_ = fma2(wm_[1], wp2[1][hp_], p_);                                     \
        p_ = fma2(wm_[2], wp2[2][hp_], p_);                                     \
        p_ = fma2(wm_[3], wp2[3][hp_], p_);                                     \
        float lo_, hi_; upk2(p_, lo_, hi_);                                     \
        lo_ = fmaxf(lo_, 0.f); hi_ = fmaxf(hi_, 0.f);                           \
        rp[hp_] = pk2(lo_, hi_);                                                \
    }                                                                           \
} while (0)

__global__ void __launch_bounds__(256) kernelB(
        const float* __restrict__ V,
        const float* __restrict__ Lambda,
        const float* __restrict__ pW1, const float* __restrict__ pb1,
        const float* __restrict__ pW2, const float* __restrict__ pb2,
        const float* __restrict__ Wp1, const float* __restrict__ bp1,
        const int*   __restrict__ batch,
        const int*   __restrict__ edge_index)
{
    extern __shared__ float sm[];
    int n = threadIdx.x;

    // ======================= CSR blocks =======================
    if (blockIdx.x >= NB) {
        int b = blockIdx.x - NB;
        int t = n;
        int* ism  = (int*)sm;
        int* cnt  = ism;             // 256
        int* cur  = ism + NN;        // 256
        int* wsum = ism + 2*NN;      // 8
        int* dstc = ism + 2*NN + 8;  // 4096

        int base = b*NN;
        cnt[t] = 0;
        __syncthreads();

        const int* srcp = edge_index + (size_t)b*EPG;
        const int* dstp = edge_index + (size_t)EDGES + (size_t)b*EPG;

        #pragma unroll
        for (int e = t; e < EPG; e += 256) {
            int d = dstp[e] - base;
            dstc[e] = d;
            atomicAdd(&cnt[d], 1);
        }
        __syncthreads();

        int v = cnt[t];
        int incl = v;
        #pragma unroll
        for (int off = 1; off < 32; off <<= 1) {
            int x = __shfl_up_sync(0xffffffffu, incl, off);
            if ((t & 31) >= off) incl += x;
        }
        if ((t & 31) == 31) wsum[t >> 5] = incl;
        __syncthreads();
        if (t == 0) {
            int s = 0;
            #pragma unroll
            for (int i = 0; i < 8; i++) { int x = wsum[i]; wsum[i] = s; s += x; }
        }
        __syncthreads();
        int excl = incl - v + wsum[t >> 5];
        g_start[b*(NN+1) + t] = excl;
        if (t == 0) g_start[b*(NN+1) + NN] = EPG;
        cur[t] = excl;
        __syncthreads();

        #pragma unroll
        for (int e = t; e < EPG; e += 256) {
            int pos = atomicAdd(&cur[dstc[e]], 1);
            g_srt[(size_t)b*EPG + pos] = srcp[e] - base;
        }
        return;
    }

    // ======================= pairwise blocks =======================
    float* Vs    = sm;                   // 5120 floats
    float* xchLo = sm + NN*VPAD;         // 4 buffers of 5120 (groups even)
    float* xchHi = sm + 5*NN*VPAD;       // 4 buffers of 5120 (groups odd)
    float* zs    = sm + 9*NN*VPAD;       // 64
    __shared__ int bnds[2];

    int b = blockIdx.x;

    // Load V tile [256 x 16] into padded smem
    const float4* vg = (const float4*)(V + (size_t)b*NN*DPE);
    for (int i = n; i < NN*DPE/4; i += 256) {
        float4 v = vg[i];
        *(float4*)&Vs[(i >> 2)*VPAD + ((i & 3) << 2)] = v;
    }

    // psi MLP (threads 0..63), eigen-count via binary search (threads 0,1)
    float pacc = 0.f;
    if (n < DPE*MM) {
        int d = n >> 2, m = n & 3;
        float lam = Lambda[b*DPE + d];
        pacc = pb2[m];
        #pragma unroll
        for (int h = 0; h < HPSI; h++) {
            float v = fmaf(lam, pW1[m*HPSI + h], pb1[m*HPSI + h]);
            pacc = fmaf(fmaxf(v, 0.f), pW2[m*HPSI + h], pacc);
        }
    }
    if (n < 2) {
        int key = b + n;            // first index with batch[i] >= key
        int lo = 0, hi = NSUM;
        while (lo < hi) {
            int mid = (lo + hi) >> 1;
            if (batch[mid] < key) lo = mid + 1; else hi = mid;
        }
        bnds[n] = lo;
    }

    // Projection weights, packed, in registers
    u64 wp2[MM][HP/2];
    u64 bps2[HP/2];
    #pragma unroll
    for (int m = 0; m < MM; m++)
        #pragma unroll
        for (int hp = 0; hp < HP/2; hp++)
            wp2[m][hp] = pk2(Wp1[m*HP + 2*hp], Wp1[m*HP + 2*hp + 1]);
    #pragma unroll
    for (int hp = 0; hp < HP/2; hp++) bps2[hp] = pk2(bp1[2*hp], bp1[2*hp+1]);

    __syncthreads();
    if (n < DPE*MM) {
        int cnt = bnds[1] - bnds[0];
        zs[n] = ((n >> 2) < cnt) ? pacc : 0.f;
    }
    __syncthreads();

    // Per-thread packed scaled row: An2[m][j] = (V[n,2j]Z[2j,m], V[n,2j+1]Z[2j+1,m])
    u64 An2[MM][DPE/2];
    {
        const float4* vrow = (const float4*)&Vs[n*VPAD];
        #pragma unroll
        for (int q = 0; q < 4; q++) {
            float4 vv = vrow[q];
            #pragma unroll
            for (int m = 0; m < MM; m++) {
                An2[m][2*q]   = pk2(vv.x * zs[(4*q)*MM + m],   vv.y * zs[(4*q+1)*MM + m]);
                An2[m][2*q+1] = pk2(vv.z * zs[(4*q+2)*MM + m], vv.w * zs[(4*q+3)*MM + m]);
            }
        }
    }

    u64 acc2[HP/2];
    #pragma unroll
    for (int h = 0; h < HP/2; h++) acc2[h] = 0ull;

    u64 rp[8];

    // o = 0: diagonal pair (n,n) counted once
    {
        COMPUTE_R2(n);
        #pragma unroll
        for (int h = 0; h < 8; h++) acc2[h] = add2(acc2[h], rp[h]);
    }

    // 32 groups of 4 offsets; ONE barrier per group (double-buffered sets).
    for (int g = 0; g < 32; g++) {
        float* bufs = (g & 1) ? xchHi : xchLo;

        #pragma unroll
        for (int j = 0; j < 4; j++) {
            int o = 4*g + 1 + j;
            bool act = (o < 128) || (n < 128);   // o=128: lower half computes
            if (act) {
                int k = (n + o) & 255;
                COMPUTE_R2(k);
                u64* xw = (u64*)&bufs[j*NN*VPAD + n*VPAD];
                #pragma unroll
                for (int h = 0; h < 8; h++) {
                    acc2[h] = add2(acc2[h], rp[h]);
                    xw[h] = rp[h];
                }
            }
        }
        __syncthreads();
        #pragma unroll
        for (int j = 0; j < 4; j++) {
            int o = 4*g + 1 + j;
            if (o < 128 || n >= 128) {
                int p = (n - o) & 255;
                const ulonglong2* xr = (const ulonglong2*)&bufs[j*NN*VPAD + p*VPAD];
                ulonglong2 a0 = xr[0], a1 = xr[1], a2 = xr[2], a3 = xr[3];
                acc2[0] = add2(acc2[0], a0.x); acc2[1] = add2(acc2[1], a0.y);
                acc2[2] = add2(acc2[2], a1.x); acc2[3] = add2(acc2[3], a1.y);
                acc2[4] = add2(acc2[4], a2.x); acc2[5] = add2(acc2[5], a2.y);
                acc2[6] = add2(acc2[6], a3.x); acc2[7] = add2(acc2[7], a3.y);
            }
        }
    }

    ulonglong2* xo = (ulonglong2*)(g_x + (size_t)(b*NN + n)*HP);
    xo[0] = make_ulonglong2(acc2[0], acc2[1]);
    xo[1] = make_ulonglong2(acc2[2], acc2[3]);
    xo[2] = make_ulonglong2(acc2[4], acc2[5]);
    xo[3] = make_ulonglong2(acc2[6], acc2[7]);
}

// ---------------------------------------------------------------------------
// Kernel D: gather + GIN MLP. 1 CTA/graph, 512 threads = 2 threads per node.
// (Byte-identical to the 77.8/77.9us R7 version.)
// ---------------------------------------------------------------------------
__global__ void __launch_bounds__(512) kernelD(
        const float* __restrict__ Wg1, const float* __restrict__ bg1,
        const float* __restrict__ Wg2, const float* __restrict__ bg2,
        const float* __restrict__ eps, float* __restrict__ out)
{
    __shared__ __align__(16) float xs[NN*VPAD];     // 20480 B
    __shared__ __align__(16) int   srts[EPG];       // 16384 B
    __shared__ __align__(16) float Wg1s[HP*HG];     //  4096 B
    __shared__ __align__(16) float Wg2s[HG*DPE];    //  4096 B
    __shared__ __align__(16) float bg1s[HG];
    __shared__ __align__(16) float bg2s[DPE];

    int b = blockIdx.x;
    int t = threadIdx.x;         // 0..511
    int node = t >> 1;
    int half = t & 1;

    {
        const int4* sg = (const int4*)(g_srt + (size_t)b*EPG);
        int4* ss = (int4*)srts;
        #pragma unroll
        for (int i = t; i < EPG/4; i += 512) ss[i] = sg[i];
    }
    const float4* xg = (const float4*)(g_x + (size_t)b*NN*HP);
    for (int i = t; i < NN*HP/4; i += 512) {
        float4 a = xg[i];
        *(float4*)&xs[(i >> 2)*VPAD + ((i & 3) << 2)] = a;
    }
    for (int i = t; i < HP*HG;  i += 512) Wg1s[i] = Wg1[i];
    for (int i = t; i < HG*DPE; i += 512) Wg2s[i] = Wg2[i];
    if (t < HG)  bg1s[t] = bg1[t];
    if (t >= 512 - DPE) bg2s[t - (512 - DPE)] = bg2[t - (512 - DPE)];
    __syncthreads();

    int s0 = g_start[b*(NN+1) + node];
    int s1 = g_start[b*(NN+1) + node + 1];
    int mid = s0 + ((s1 - s0 + 1) >> 1);
    int lo = half ? mid : s0;
    int hi = half ? s1  : mid;

    u64 agg[8];
    #pragma unroll
    for (int j = 0; j < 8; j++) agg[j] = 0ull;

    int idx = lo;
    for (; idx + 4 <= hi; idx += 4) {
        int e0 = srts[idx], e1 = srts[idx+1], e2 = srts[idx+2], e3 = srts[idx+3];
        const ulonglong2* r0 = (const ulonglong2*)&xs[e0*VPAD];
        const ulonglong2* r1 = (const ulonglong2*)&xs[e1*VPAD];
        const ulonglong2* r2 = (const ulonglong2*)&xs[e2*VPAD];
        const ulonglong2* r3 = (const ulonglong2*)&xs[e3*VPAD];
        ulonglong2 p00=r0[0], p01=r0[1], p02=r0[2], p03=r0[3];
        ulonglong2 p10=r1[0], p11=r1[1], p12=r1[2], p13=r1[3];
        ulonglong2 p20=r2[0], p21=r2[1], p22=r2[2], p23=r2[3];
        ulonglong2 p30=r3[0], p31=r3[1], p32=r3[2], p33=r3[3];
        agg[0]=add2(agg[0],p00.x); agg[1]=add2(agg[1],p00.y);
        agg[2]=add2(agg[2],p01.x); agg[3]=add2(agg[3],p01.y);
        agg[4]=add2(agg[4],p02.x); agg[5]=add2(agg[5],p02.y);
        agg[6]=add2(agg[6],p03.x); agg[7]=add2(agg[7],p03.y);
        agg[0]=add2(agg[0],p10.x); agg[1]=add2(agg[1],p10.y);
        agg[2]=add2(agg[2],p11.x); agg[3]=add2(agg[3],p11.y);
        agg[4]=add2(agg[4],p12.x); agg[5]=add2(agg[5],p12.y);
        agg[6]=add2(agg[6],p13.x); agg[7]=add2(agg[7],p13.y);
        agg[0]=add2(agg[0],p20.x); agg[1]=add2(agg[1],p20.y);
        agg[2]=add2(agg[2],p21.x); agg[3]=add2(agg[3],p21.y);
        agg[4]=add2(agg[4],p22.x); agg[5]=add2(agg[5],p22.y);
        agg[6]=add2(agg[6],p23.x); agg[7]=add2(agg[7],p23.y);
        agg[0]=add2(agg[0],p30.x); agg[1]=add2(agg[1],p30.y);
        agg[2]=add2(agg[2],p31.x); agg[3]=add2(agg[3],p31.y);
        agg[4]=add2(agg[4],p32.x); agg[5]=add2(agg[5],p32.y);
        agg[6]=add2(agg[6],p33.x); agg[7]=add2(agg[7],p33.y);
    }
    for (; idx < hi; idx++) {
        int e = srts[idx];
        const ulonglong2* r = (const ulonglong2*)&xs[e*VPAD];
        ulonglong2 q0=r[0], q1=r[1], q2=r[2], q3=r[3];
        agg[0]=add2(agg[0],q0.x); agg[1]=add2(agg[1],q0.y);
        agg[2]=add2(agg[2],q1.x); agg[3]=add2(agg[3],q1.y);
        agg[4]=add2(agg[4],q2.x); agg[5]=add2(agg[5],q2.y);
        agg[6]=add2(agg[6],q3.x); agg[7]=add2(agg[7],q3.y);
    }

    #pragma unroll
    for (int j = 0; j < 8; j++) {
        u64 o = __shfl_xor_sync(0xffffffffu, agg[j], 1);
        agg[j] = add2(agg[j], o);
    }

    float ge = 1.f + eps[0];
    u64 ge2 = pk2(ge, ge);
    u64 yfull[8];
    {
        const ulonglong2* xself = (const ulonglong2*)&xs[node*VPAD];
        ulonglong2 q0=xself[0], q1=xself[1], q2=xself[2], q3=xself[3];
        yfull[0]=fma2(ge2,q0.x,agg[0]); yfull[1]=fma2(ge2,q0.y,agg[1]);
        yfull[2]=fma2(ge2,q1.x,agg[2]); yfull[3]=fma2(ge2,q1.y,agg[3]);
        yfull[4]=fma2(ge2,q2.x,agg[4]); yfull[5]=fma2(ge2,q2.y,agg[5]);
        yfull[6]=fma2(ge2,q3.x,agg[6]); yfull[7]=fma2(ge2,q3.y,agg[7]);
    }

    u64 tg[16];
    {
        const u64* bu = (const u64*)bg1s;
        #pragma unroll
        for (int j = 0; j < 16; j++) tg[j] = bu[16*half + j];
    }
    #pragma unroll
    for (int hq = 0; hq < 8; hq++) {
        float ylo, yhi; upk2(yfull[hq], ylo, yhi);
        u64 ya = pk2(ylo, ylo), yb = pk2(yhi, yhi);
        const u64* wa = (const u64*)&Wg1s[(2*hq)*HG   + 32*half];
        const u64* wb = (const u64*)&Wg1s[(2*hq+1)*HG + 32*half];
        #pragma unroll
        for (int j = 0; j < 16; j++) {
            tg[j] = fma2(ya, wa[j], tg[j]);
            tg[j] = fma2(yb, wb[j], tg[j]);
        }
    }

    u64 o2[8];
    {
        const u64* bu = (const u64*)bg2s;
        #pragma unroll
        for (int d = 0; d < 8; d++) o2[d] = half ? 0ull : bu[d];
    }
    #pragma unroll
    for (int j = 0; j < 16; j++) {
        float t0, t1; upk2(tg[j], t0, t1);
        t0 = fmaxf(t0, 0.f); t1 = fmaxf(t1, 0.f);
        u64 ta = pk2(t0, t0), tb = pk2(t1, t1);
        int r0 = 32*half + 2*j;
        const u64* wa = (const u64*)&Wg2s[r0*DPE];
        const u64* wb = (const u64*)&Wg2s[(r0+1)*DPE];
        #pragma unroll
        for (int d = 0; d < 8; d++) {
            o2[d] = fma2(ta, wa[d], o2[d]);
            o2[d] = fma2(tb, wb[d], o2[d]);
        }
    }
    #pragma unroll
    for (int d = 0; d < 8; d++) {
        u64 oo = __shfl_xor_sync(0xffffffffu, o2[d], 1);
        o2[d] = add2(o2[d], oo);
    }

    if (half == 0) {
        ulonglong2* op = (ulonglong2*)(out + (size_t)(b*NN + node)*DPE);
        op[0] = make_ulonglong2(o2[0], o2[1]);
        op[1] = make_ulonglong2(o2[2], o2[3]);
        op[2] = make_ulonglong2(o2[4], o2[5]);
        op[3] = make_ulonglong2(o2[6], o2[7]);
    }
}

// ---------------------------------------------------------------------------
extern "C" void kernel_launch(void* const* d_in, const int* in_sizes, int n_in,
                              void* d_out, int out_size)
{
    const float* Lambda = (const float*)d_in[0];
    const float* V      = (const float*)d_in[1];
    const float* pW1    = (const float*)d_in[2];
    const float* pb1    = (const float*)d_in[3];
    const float* pW2    = (const float*)d_in[4];
    const float* pb2    = (const float*)d_in[5];
    const float* Wp1    = (const float*)d_in[6];
    const float* bp1    = (const float*)d_in[7];
    const float* Wg1    = (const float*)d_in[8];
    const float* bg1    = (const float*)d_in[9];
    const float* Wg2    = (const float*)d_in[10];
    const float* bg2    = (const float*)d_in[11];
    const float* eps    = (const float*)d_in[12];
    const int*   edge_index = (const int*)d_in[13];
    const int*   batch  = (const int*)d_in[14];
    float* out = (float*)d_out;

    // V + 8 exchange buffers + zs: (9*NN*VPAD + 64) floats = 184576 bytes
    const int smemB = (9*NN*VPAD + 64) * (int)sizeof(float);
    cudaFuncSetAttribute(kernelB, cudaFuncAttributeMaxDynamicSharedMemorySize, smemB);

    kernelB<<<NB*2, 256, smemB>>>(V, Lambda, pW1, pb1, pW2, pb2, Wp1, bp1,
                                  batch, edge_index);
    kernelD<<<NB, 512>>>(Wg1, bg1, Wg2, bg2, eps, out);
}

// round 12
// speedup vs baseline: 1.3366x; 1.1018x over previous
#include <cuda_runtime.h>

// Problem constants (fixed by the dataset)
#define NB    128          // graphs (B)
#define NN    256          // nodes per graph
#define DPE   16           // D_pe / eigen dim
#define MM    4            // M psi copies
#define HPSI  32
#define HP    16
#define HG    64
#define NSUM  (NB*NN)      // 32768
#define EDGES (NSUM*16)    // 524288
#define EPG   (EDGES/NB)   // 4096 edges per graph (graph-contiguous)
#define VPAD  20           // padded row stride (floats)

typedef unsigned long long u64;

// ---------------- packed f32x2 helpers ----------------
__device__ __forceinline__ u64 pk2(float lo, float hi) {
    u64 r; asm("mov.b64 %0,{%1,%2};" : "=l"(r) : "f"(lo), "f"(hi)); return r;
}
__device__ __forceinline__ void upk2(u64 v, float& lo, float& hi) {
    asm("mov.b64 {%0,%1},%2;" : "=f"(lo), "=f"(hi) : "l"(v));
}
__device__ __forceinline__ u64 fma2(u64 a, u64 b, u64 c) {
    u64 d; asm("fma.rn.f32x2 %0,%1,%2,%3;" : "=l"(d) : "l"(a), "l"(b), "l"(c)); return d;
}
__device__ __forceinline__ u64 mul2(u64 a, u64 b) {
    u64 d; asm("mul.rn.f32x2 %0,%1,%2;" : "=l"(d) : "l"(a), "l"(b)); return d;
}
__device__ __forceinline__ u64 add2(u64 a, u64 b) {
    u64 d; asm("add.rn.f32x2 %0,%1,%2;" : "=l"(d) : "l"(a), "l"(b)); return d;
}

// ---------------------------------------------------------------------------
// ONE fused kernel per graph: CSR build -> psi/mask -> pairwise o-loop ->
// in-smem GIN gather + output MLP. Grid = NB blocks of 256 threads.
// ---------------------------------------------------------------------------
#define COMPUTE_R2(kk) do {                                                     \
    const ulonglong2* vr_ = (const ulonglong2*)&Vs[(kk)*VPAD];                  \
    ulonglong2 a_ = vr_[0], b_ = vr_[1], c_ = vr_[2], d_ = vr_[3];              \
    u64 vk_[8] = {a_.x, a_.y, b_.x, b_.y, c_.x, c_.y, d_.x, d_.y};              \
    u64 wm_[4];                                                                 \
    _Pragma("unroll")                                                           \
    for (int m_ = 0; m_ < 4; m_++) {                                            \
        u64 s_ = mul2(An2[m_][0], vk_[0]);                                      \
        _Pragma("unroll")                                                       \
        for (int j_ = 1; j_ < 8; j_++) s_ = fma2(An2[m_][j_], vk_[j_], s_);     \
        float lo_, hi_; upk2(s_, lo_, hi_);                                     \
        float w_ = lo_ + hi_;                                                   \
        wm_[m_] = pk2(w_, w_);                                                  \
    }                                                                           \
    _Pragma("unroll")                                                           \
    for (int hp_ = 0; hp_ < 8; hp_++) {                                         \
        u64 p_ = fma2(wm_[0], wp2[0][hp_], bps2[hp_]);                          \
        p_ = fma2(wm_[1], wp2[1][hp_], p_);                                     \
        p_ = fma2(wm_[2], wp2[2][hp_], p_);                                     \
        p_ = fma2(wm_[3], wp2[3][hp_], p_);                                     \
        float lo_, hi_; upk2(p_, lo_, hi_);                                     \
        lo_ = fmaxf(lo_, 0.f); hi_ = fmaxf(hi_, 0.f);                           \
        rp[hp_] = pk2(lo_, hi_);                                                \
    }                                                                           \
} while (0)

__global__ void __launch_bounds__(256) kernelF(
        const float* __restrict__ V,
        const float* __restrict__ Lambda,
        const float* __restrict__ pW1, const float* __restrict__ pb1,
        const float* __restrict__ pW2, const float* __restrict__ pb2,
        const float* __restrict__ Wp1, const float* __restrict__ bp1,
        const float* __restrict__ Wg1, const float* __restrict__ bg1,
        const float* __restrict__ Wg2, const float* __restrict__ bg2,
        const float* __restrict__ eps,
        const int*   __restrict__ batch,
        const int*   __restrict__ edge_index,
        float* __restrict__ out)
{
    extern __shared__ float sm[];
    // Persistent regions
    float* Vs      = sm;                         // 5120 floats
    float* xch     = sm + NN*VPAD;               // 8 buffers x 5120
    float* zs      = sm + 9*NN*VPAD;             // 64
    int*   srt_s   = (int*)(sm + 9*NN*VPAD + 64);        // 4096 ints
    int*   start_s = (int*)(sm + 9*NN*VPAD + 64 + 4096); // 257 ints
    __shared__ int bnds[2];
    __shared__ int wsum[8];

    // Phase-limited aliases (CSR build, pre-o-loop) inside xch:
    int* cnt  = (int*)xch;          // 256
    int* cur  = cnt + NN;           // 256
    int* dstc = cur + NN;           // 4096

    // Phase-limited aliases (epilogue) inside xch:
    float* xT   = xch;              // 5120 (x tile)
    float* Wg1s = xch + NN*VPAD;    // 1024
    float* Wg2s = Wg1s + HP*HG;     // 1024
    float* bg1s = Wg2s + HG*DPE;    // 64
    float* bg2s = bg1s + HG;        // 16

    int b = blockIdx.x;
    int n = threadIdx.x;

    // ---- Stage V tile [256 x 16] into padded smem ----
    const float4* vg = (const float4*)(V + (size_t)b*NN*DPE);
    for (int i = n; i < NN*DPE/4; i += 256) {
        float4 v = vg[i];
        *(float4*)&Vs[(i >> 2)*VPAD + ((i & 3) << 2)] = v;
    }

    // ---- psi MLP (threads 0..63) + eigen-count binary search (threads 0,1) ----
    float pacc = 0.f;
    if (n < DPE*MM) {
        int d = n >> 2, m = n & 3;
        float lam = Lambda[b*DPE + d];
        pacc = pb2[m];
        #pragma unroll
        for (int h = 0; h < HPSI; h++) {
            float v = fmaf(lam, pW1[m*HPSI + h], pb1[m*HPSI + h]);
            pacc = fmaf(fmaxf(v, 0.f), pW2[m*HPSI + h], pacc);
        }
    }
    if (n < 2) {
        int key = b + n;            // first index with batch[i] >= key
        int lo = 0, hi = NSUM;
        while (lo < hi) {
            int mid = (lo + hi) >> 1;
            if (batch[mid] < key) lo = mid + 1; else hi = mid;
        }
        bnds[n] = lo;
    }

    // ---- Projection weights, packed, in registers ----
    u64 wp2[MM][HP/2];
    u64 bps2[HP/2];
    #pragma unroll
    for (int m = 0; m < MM; m++)
        #pragma unroll
        for (int hp = 0; hp < HP/2; hp++)
            wp2[m][hp] = pk2(Wp1[m*HP + 2*hp], Wp1[m*HP + 2*hp + 1]);
    #pragma unroll
    for (int hp = 0; hp < HP/2; hp++) bps2[hp] = pk2(bp1[2*hp], bp1[2*hp+1]);

    // ---- CSR build (uses cnt/cur/dstc aliased into xch) ----
    cnt[n] = 0;
    __syncthreads();

    const int* srcp = edge_index + (size_t)b*EPG;
    const int* dstp = edge_index + (size_t)EDGES + (size_t)b*EPG;
    int base = b*NN;

    #pragma unroll
    for (int e = n; e < EPG; e += 256) {
        int d = dstp[e] - base;
        dstc[e] = d;
        atomicAdd(&cnt[d], 1);
    }
    __syncthreads();

    {
        int v = cnt[n];
        int incl = v;
        #pragma unroll
        for (int off = 1; off < 32; off <<= 1) {
            int x = __shfl_up_sync(0xffffffffu, incl, off);
            if ((n & 31) >= off) incl += x;
        }
        if ((n & 31) == 31) wsum[n >> 5] = incl;
        __syncthreads();
        if (n == 0) {
            int s = 0;
            #pragma unroll
            for (int i = 0; i < 8; i++) { int x = wsum[i]; wsum[i] = s; s += x; }
        }
        __syncthreads();
        int excl = incl - v + wsum[n >> 5];
        start_s[n] = excl;
        if (n == 0) start_s[NN] = EPG;
        cur[n] = excl;
    }
    __syncthreads();

    #pragma unroll
    for (int e = n; e < EPG; e += 256) {
        int pos = atomicAdd(&cur[dstc[e]], 1);
        srt_s[pos] = srcp[e] - base;
    }

    // ---- masked Z ----
    if (n < DPE*MM) {
        int c = bnds[1] - bnds[0];
        zs[n] = ((n >> 2) < c) ? pacc : 0.f;
    }
    __syncthreads();   // zs + srt_s visible; CSR temps (in xch) done

    // ---- Per-thread packed scaled row ----
    u64 An2[MM][DPE/2];
    {
        const float4* vrow = (const float4*)&Vs[n*VPAD];
        #pragma unroll
        for (int q = 0; q < 4; q++) {
            float4 vv = vrow[q];
            #pragma unroll
            for (int m = 0; m < MM; m++) {
                An2[m][2*q]   = pk2(vv.x * zs[(4*q)*MM + m],   vv.y * zs[(4*q+1)*MM + m]);
                An2[m][2*q+1] = pk2(vv.z * zs[(4*q+2)*MM + m], vv.w * zs[(4*q+3)*MM + m]);
            }
        }
    }

    u64 acc2[HP/2];
    #pragma unroll
    for (int h = 0; h < HP/2; h++) acc2[h] = 0ull;

    u64 rp[8];

    // o = 0: diagonal pair (n,n) counted once
    {
        COMPUTE_R2(n);
        #pragma unroll
        for (int h = 0; h < 8; h++) acc2[h] = add2(acc2[h], rp[h]);
    }

    // 32 groups of 4 offsets; ONE barrier per group (double-buffered sets).
    float* xchLo = xch;
    float* xchHi = xch + 4*NN*VPAD;
    for (int g = 0; g < 32; g++) {
        float* bufs = (g & 1) ? xchHi : xchLo;

        #pragma unroll
        for (int j = 0; j < 4; j++) {
            int o = 4*g + 1 + j;
            bool act = (o < 128) || (n < 128);   // o=128: lower half computes
            if (act) {
                int k = (n + o) & 255;
                COMPUTE_R2(k);
                u64* xw = (u64*)&bufs[j*NN*VPAD + n*VPAD];
                #pragma unroll
                for (int h = 0; h < 8; h++) {
                    acc2[h] = add2(acc2[h], rp[h]);
                    xw[h] = rp[h];
                }
            }
        }
        __syncthreads();
        #pragma unroll
        for (int j = 0; j < 4; j++) {
            int o = 4*g + 1 + j;
            if (o < 128 || n >= 128) {
                int p = (n - o) & 255;
                const ulonglong2* xr = (const ulonglong2*)&bufs[j*NN*VPAD + p*VPAD];
                ulonglong2 a0 = xr[0], a1 = xr[1], a2 = xr[2], a3 = xr[3];
                acc2[0] = add2(acc2[0], a0.x); acc2[1] = add2(acc2[1], a0.y);
                acc2[2] = add2(acc2[2], a1.x); acc2[3] = add2(acc2[3], a1.y);
                acc2[4] = add2(acc2[4], a2.x); acc2[5] = add2(acc2[5], a2.y);
                acc2[6] = add2(acc2[6], a3.x); acc2[7] = add2(acc2[7], a3.y);
            }
        }
    }
    __syncthreads();   // all exchange reads complete; xch reusable

    // ---- Epilogue: write x tile, stage GIN weights (alias into xch) ----
    {
        ulonglong2* xw = (ulonglong2*)&xT[n*VPAD];
        xw[0] = make_ulonglong2(acc2[0], acc2[1]);
        xw[1] = make_ulonglong2(acc2[2], acc2[3]);
        xw[2] = make_ulonglong2(acc2[4], acc2[5]);
        xw[3] = make_ulonglong2(acc2[6], acc2[7]);
    }
    #pragma unroll
    for (int i = n; i < HP*HG; i += 256)  Wg1s[i] = Wg1[i];
    #pragma unroll
    for (int i = n; i < HG*DPE; i += 256) Wg2s[i] = Wg2[i];
    if (n < HG)  bg1s[n] = bg1[n];
    if (n >= 256 - DPE) bg2s[n - (256 - DPE)] = bg2[n - (256 - DPE)];
    float ge = 1.f + eps[0];
    __syncthreads();

    // ---- GIN gather (in-smem CSR) ----
    u64 agg[8];
    #pragma unroll
    for (int j = 0; j < 8; j++) agg[j] = 0ull;
    {
        int s0 = start_s[n], s1 = start_s[n + 1];
        int idx = s0;
        for (; idx + 2 <= s1; idx += 2) {
            int ea = srt_s[idx], eb = srt_s[idx + 1];
            const ulonglong2* ra = (const ulonglong2*)&xT[ea*VPAD];
            const ulonglong2* rb = (const ulonglong2*)&xT[eb*VPAD];
            ulonglong2 a0=ra[0], a1=ra[1], a2=ra[2], a3=ra[3];
            ulonglong2 b0=rb[0], b1=rb[1], b2=rb[2], b3=rb[3];
            agg[0]=add2(agg[0],a0.x); agg[1]=add2(agg[1],a0.y);
            agg[2]=add2(agg[2],a1.x); agg[3]=add2(agg[3],a1.y);
            agg[4]=add2(agg[4],a2.x); agg[5]=add2(agg[5],a2.y);
            agg[6]=add2(agg[6],a3.x); agg[7]=add2(agg[7],a3.y);
            agg[0]=add2(agg[0],b0.x); agg[1]=add2(agg[1],b0.y);
            agg[2]=add2(agg[2],b1.x); agg[3]=add2(agg[3],b1.y);
            agg[4]=add2(agg[4],b2.x); agg[5]=add2(agg[5],b2.y);
            agg[6]=add2(agg[6],b3.x); agg[7]=add2(agg[7],b3.y);
        }
        if (idx < s1) {
            int e = srt_s[idx];
            const ulonglong2* r = (const ulonglong2*)&xT[e*VPAD];
            ulonglong2 q0=r[0], q1=r[1], q2=r[2], q3=r[3];
            agg[0]=add2(agg[0],q0.x); agg[1]=add2(agg[1],q0.y);
            agg[2]=add2(agg[2],q1.x); agg[3]=add2(agg[3],q1.y);
            agg[4]=add2(agg[4],q2.x); agg[5]=add2(agg[5],q2.y);
            agg[6]=add2(agg[6],q3.x); agg[7]=add2(agg[7],q3.y);
        }
    }

    // y = (1+eps)*x_self + agg  (x_self = acc2 still in registers!)
    u64 ge2 = pk2(ge, ge);
    u64 yfull[8];
    #pragma unroll
    for (int j = 0; j < 8; j++) yfull[j] = fma2(ge2, acc2[j], agg[j]);

    // Layer 1: tg[64] = y @ Wg1 + bg1 (full, per thread)
    u64 tg[HG/2];
    {
        const u64* bu = (const u64*)bg1s;
        #pragma unroll
        for (int j = 0; j < HG/2; j++) tg[j] = bu[j];
    }
    #pragma unroll
    for (int hq = 0; hq < 8; hq++) {
        float ylo, yhi; upk2(yfull[hq], ylo, yhi);
        u64 ya = pk2(ylo, ylo), yb = pk2(yhi, yhi);
        const u64* wa = (const u64*)&Wg1s[(2*hq)*HG];
        const u64* wb = (const u64*)&Wg1s[(2*hq+1)*HG];
        #pragma unroll
        for (int j = 0; j < HG/2; j++) {
            tg[j] = fma2(ya, wa[j], tg[j]);
            tg[j] = fma2(yb, wb[j], tg[j]);
        }
    }

    // ReLU + layer 2: out[16] = relu(tg) @ Wg2 + bg2
    u64 o2[DPE/2];
    {
        const u64* bu = (const u64*)bg2s;
        #pragma unroll
        for (int d = 0; d < DPE/2; d++) o2[d] = bu[d];
    }
    #pragma unroll
    for (int j = 0; j < HG/2; j++) {
        float t0, t1; upk2(tg[j], t0, t1);
        t0 = fmaxf(t0, 0.f); t1 = fmaxf(t1, 0.f);
        u64 ta = pk2(t0, t0), tb = pk2(t1, t1);
        const u64* wa = (const u64*)&Wg2s[(2*j)*DPE];
        const u64* wb = (const u64*)&Wg2s[(2*j+1)*DPE];
        #pragma unroll
        for (int d = 0; d < DPE/2; d++) {
            o2[d] = fma2(ta, wa[d], o2[d]);
            o2[d] = fma2(tb, wb[d], o2[d]);
        }
    }

    ulonglong2* op = (ulonglong2*)(out + (size_t)(b*NN + n)*DPE);
    op[0] = make_ulonglong2(o2[0], o2[1]);
    op[1] = make_ulonglong2(o2[2], o2[3]);
    op[2] = make_ulonglong2(o2[4], o2[5]);
    op[3] = make_ulonglong2(o2[6], o2[7]);
}

// ---------------------------------------------------------------------------
extern "C" void kernel_launch(void* const* d_in, const int* in_sizes, int n_in,
                              void* d_out, int out_size)
{
    const float* Lambda = (const float*)d_in[0];
    const float* V      = (const float*)d_in[1];
    const float* pW1    = (const float*)d_in[2];
    const float* pb1    = (const float*)d_in[3];
    const float* pW2    = (const float*)d_in[4];
    const float* pb2    = (const float*)d_in[5];
    const float* Wp1    = (const float*)d_in[6];
    const float* bp1    = (const float*)d_in[7];
    const float* Wg1    = (const float*)d_in[8];
    const float* bg1    = (const float*)d_in[9];
    const float* Wg2    = (const float*)d_in[10];
    const float* bg2    = (const float*)d_in[11];
    const float* eps    = (const float*)d_in[12];
    const int*   edge_index = (const int*)d_in[13];
    const int*   batch  = (const int*)d_in[14];
    float* out = (float*)d_out;

    // V(5120) + xch(40960) + zs(64) + srt(4096) + start(257) floats
    const int smemF = (9*NN*VPAD + 64 + 4096 + 257 + 3) * (int)sizeof(float); // 202060 B
    cudaFuncSetAttribute(kernelF, cudaFuncAttributeMaxDynamicSharedMemorySize, smemF);

    kernelF<<<NB, 256, smemF>>>(V, Lambda, pW1, pb1, pW2, pb2, Wp1, bp1,
                                Wg1, bg1, Wg2, bg2, eps, batch, edge_index, out);
}